// round 1
// baseline (speedup 1.0000x reference)
#include <cuda_runtime.h>
#include <cuda_bf16.h>

// Problem constants
#define BB 4
#define SS 4096
#define DD 2048
#define LL 3
#define TRIPLE (3 * DD)

// Scratch (allocation-free rule: __device__ globals)
__device__ float g_BCx[(size_t)BB * SS * TRIPLE];   // 402 MB: [b,s,3D] = [B_gate | C_gate | x_proj]
__device__ float g_y[(size_t)BB * SS * DD];         // 134 MB

// ---------------------------------------------------------------------------
// Classic fp32 SGEMM: C[M,N] = A[M,K] @ B[K,N], all row-major.
// BM=128, BN=128, BK=16, per-thread 8x8, 256 threads.
// Requires M%128==0, N%128==0, K%16==0 (true for all our shapes).
// ---------------------------------------------------------------------------
template <int BM, int BN, int BK, int TM, int TN>
__global__ __launch_bounds__(256, 2)
void sgemm_kernel(const float* __restrict__ A,
                  const float* __restrict__ B,
                  float* __restrict__ C,
                  int M, int N, int K) {
    __shared__ float As[BK][BM];
    __shared__ float Bs[BK][BN];

    const int tid = threadIdx.x;
    const int tx  = tid % (BN / TN);   // 0..15
    const int ty  = tid / (BN / TN);   // 0..15

    const int block_row = blockIdx.y;
    const int block_col = blockIdx.x;

    const float* Aptr = A + (size_t)block_row * BM * K;
    const float* Bptr = B + (size_t)block_col * BN;

    float acc[TM][TN];
    #pragma unroll
    for (int i = 0; i < TM; i++)
        #pragma unroll
        for (int j = 0; j < TN; j++)
            acc[i][j] = 0.0f;

    float areg[TM], breg[TN];

    for (int kt = 0; kt < K; kt += BK) {
        // Load A tile (BM x BK) -> transposed into As[BK][BM]
        #pragma unroll
        for (int i = 0; i < (BM * BK) / (256 * 4); i++) {
            int f   = tid + i * 256;          // float4 index, 0..511
            int row = f / (BK / 4);           // 0..127
            int c4  = f % (BK / 4);           // 0..3
            float4 v = *(const float4*)(Aptr + (size_t)row * K + kt + c4 * 4);
            As[c4 * 4 + 0][row] = v.x;
            As[c4 * 4 + 1][row] = v.y;
            As[c4 * 4 + 2][row] = v.z;
            As[c4 * 4 + 3][row] = v.w;
        }
        // Load B tile (BK x BN)
        #pragma unroll
        for (int i = 0; i < (BK * BN) / (256 * 4); i++) {
            int f   = tid + i * 256;          // 0..511
            int row = f / (BN / 4);           // 0..15
            int c4  = f % (BN / 4);           // 0..31
            *(float4*)(&Bs[row][c4 * 4]) =
                *(const float4*)(Bptr + (size_t)(kt + row) * N + c4 * 4);
        }
        __syncthreads();

        #pragma unroll
        for (int k = 0; k < BK; k++) {
            #pragma unroll
            for (int i = 0; i < TM; i++) areg[i] = As[k][ty * TM + i];
            #pragma unroll
            for (int j = 0; j < TN; j++) breg[j] = Bs[k][tx * TN + j];
            #pragma unroll
            for (int i = 0; i < TM; i++)
                #pragma unroll
                for (int j = 0; j < TN; j++)
                    acc[i][j] += areg[i] * breg[j];
        }
        __syncthreads();
    }

    float* Cptr = C + (size_t)(block_row * BM + ty * TM) * N
                    + block_col * BN + tx * TN;
    #pragma unroll
    for (int i = 0; i < TM; i++) {
        #pragma unroll
        for (int j = 0; j < TN; j += 4) {
            float4 v = make_float4(acc[i][j], acc[i][j + 1],
                                   acc[i][j + 2], acc[i][j + 3]);
            *(float4*)(Cptr + (size_t)i * N + j) = v;
        }
    }
}

// ---------------------------------------------------------------------------
// Fused: Bx = B_gate * x_proj; causal depthwise conv (L=3, per-batch);
//        y = C_gate * conv_out.
// conv_out[s] = w[d,0]*Bx[s-2] + w[d,1]*Bx[s-1] + w[d,2]*Bx[s]
// One thread handles 4 consecutive d (float4).
// ---------------------------------------------------------------------------
__global__ void conv_gate_kernel(const float* __restrict__ conv_w,
                                 float* __restrict__ y) {
    const size_t total = (size_t)BB * SS * (DD / 4);
    size_t idx = (size_t)blockIdx.x * blockDim.x + threadIdx.x;
    if (idx >= total) return;

    const int    d4 = (int)(idx % (DD / 4));
    const size_t bs = idx / (DD / 4);
    const int    s  = (int)(bs % SS);
    const int    d  = d4 * 4;

    const float* base = g_BCx + bs * TRIPLE;   // row (b,s) in BCx
    const float* bm1  = base - TRIPLE;         // row (b,s-1)
    const float* bm2  = base - 2 * TRIPLE;     // row (b,s-2)

    float out[4];
    #pragma unroll
    for (int j = 0; j < 4; j++) {
        const int dj = d + j;
        const float w0 = conv_w[dj * LL + 0];
        const float w1 = conv_w[dj * LL + 1];
        const float w2 = conv_w[dj * LL + 2];

        float bx_s  = base[dj] * base[2 * DD + dj];
        float bx_s1 = (s >= 1) ? bm1[dj] * bm1[2 * DD + dj] : 0.0f;
        float bx_s2 = (s >= 2) ? bm2[dj] * bm2[2 * DD + dj] : 0.0f;

        float conv = w2 * bx_s + w1 * bx_s1 + w0 * bx_s2;
        out[j] = base[DD + dj] * conv;
    }
    *(float4*)(g_y + bs * DD + d) = *(float4*)out;
}

// ---------------------------------------------------------------------------
extern "C" void kernel_launch(void* const* d_in, const int* in_sizes, int n_in,
                              void* d_out, int out_size) {
    const float* x      = (const float*)d_in[0];
    const float* W_in   = (const float*)d_in[1];
    const float* conv_w = (const float*)d_in[2];
    const float* W_out  = (const float*)d_in[3];
    float*       out    = (float*)d_out;

    float* BCx = nullptr;
    float* y   = nullptr;
    cudaGetSymbolAddress((void**)&BCx, g_BCx);
    cudaGetSymbolAddress((void**)&y,   g_y);

    const int M = BB * SS;   // 16384

    // GEMM1: BCx = x @ W_in   (M x 2048) @ (2048 x 6144)
    {
        dim3 grid(TRIPLE / 128, M / 128);
        sgemm_kernel<128, 128, 16, 8, 8><<<grid, 256>>>(x, W_in, BCx, M, TRIPLE, DD);
    }

    // Conv + gates -> y
    {
        const size_t total = (size_t)BB * SS * (DD / 4);
        int threads = 256;
        int blocks  = (int)((total + threads - 1) / threads);
        conv_gate_kernel<<<blocks, threads>>>(conv_w, y);
    }

    // GEMM2: out = y @ W_out  (M x 2048) @ (2048 x 2048)
    {
        dim3 grid(DD / 128, M / 128);
        sgemm_kernel<128, 128, 16, 8, 8><<<grid, 256>>>(y, W_out, out, M, DD, DD);
    }
}

// round 2
// speedup vs baseline: 1.7854x; 1.7854x over previous
#include <cuda_runtime.h>
#include <cuda_bf16.h>
#include <cstdint>

// Problem constants
#define BB 4
#define SS 4096
#define DD 2048
#define LL 3
#define TRIPLE (3 * DD)

#define BM 128
#define BN 128
#define BKT 32
#define ASZ (BM * 36)      // A smem floats per buffer (pad row to 36)
#define BSZ (BKT * 132)    // B smem floats per buffer (pad row to 132)
#define SMEM_BYTES (2 * (ASZ + BSZ) * 4)

// Scratch (allocation-free rule: __device__ globals)
__device__ float g_BCx[(size_t)BB * SS * TRIPLE];   // [b,s,3D] = [B_gate | C_gate | x_proj]
__device__ float g_y[(size_t)BB * SS * DD];

__device__ __forceinline__ float f2tf32(float x) {
    float r;
    asm("cvt.rna.tf32.f32 %0, %1;" : "=f"(r) : "f"(x));
    return r;
}

__device__ __forceinline__ void mma_tf32(float c[4], const uint32_t a[4], const uint32_t b[2]) {
    asm volatile(
        "mma.sync.aligned.m16n8k8.row.col.f32.tf32.tf32.f32 "
        "{%0,%1,%2,%3}, {%4,%5,%6,%7}, {%8,%9}, {%0,%1,%2,%3};"
        : "+f"(c[0]), "+f"(c[1]), "+f"(c[2]), "+f"(c[3])
        : "r"(a[0]), "r"(a[1]), "r"(a[2]), "r"(a[3]), "r"(b[0]), "r"(b[1]));
}

// ---------------------------------------------------------------------------
// TF32 tensor-core GEMM: C[M,N] = A[M,K] @ B[K,N], row-major fp32 in/out.
// 256 threads, BM=128, BN=128, BK=32. Warp grid 2x4 (m x n), warp tile 64x32.
// Requires M%128==0, N%128==0, K%32==0.
// ---------------------------------------------------------------------------
__global__ __launch_bounds__(256, 1)
void tf32_gemm(const float* __restrict__ A, const float* __restrict__ B,
               float* __restrict__ C, int N, int K) {
    extern __shared__ float sm[];
    float* AsBase = sm;               // [2][ASZ]
    float* BsBase = sm + 2 * ASZ;     // [2][BSZ]

    const int tid    = threadIdx.x;
    const int wid    = tid >> 5;
    const int lane   = tid & 31;
    const int warp_m = wid >> 2;      // 0..1
    const int warp_n = wid & 3;       // 0..3
    const int lr     = lane >> 2;     // 0..7
    const int lc     = lane & 3;      // 0..3

    const int brow = blockIdx.y * BM;
    const int bcol = blockIdx.x * BN;

    const float* Ap = A + (size_t)brow * K;
    const float* Bp = B + bcol;

    float acc[4][4][4];
    #pragma unroll
    for (int mi = 0; mi < 4; mi++)
        #pragma unroll
        for (int ni = 0; ni < 4; ni++)
            #pragma unroll
            for (int t = 0; t < 4; t++)
                acc[mi][ni][t] = 0.0f;

    // Per-thread global-load coords (4 float4 each for A and B)
    // A: f = tid + i*256 -> row = f/8 (0..127), c4 = f%8
    // B: f -> row = f/32 (0..31), c4 = f%32
    float4 ra[4], rb[4];

    auto load_global = [&](int kt) {
        #pragma unroll
        for (int i = 0; i < 4; i++) {
            int f = tid + i * 256;
            int arow = f >> 3, ac4 = f & 7;
            ra[i] = *(const float4*)(Ap + (size_t)arow * K + kt * BKT + ac4 * 4);
            int browk = f >> 5, bc4 = f & 31;
            rb[i] = *(const float4*)(Bp + (size_t)(kt * BKT + browk) * N + bc4 * 4);
        }
    };

    auto store_smem = [&](int buf) {
        float* As = AsBase + buf * ASZ;
        float* Bs = BsBase + buf * BSZ;
        #pragma unroll
        for (int i = 0; i < 4; i++) {
            int f = tid + i * 256;
            int arow = f >> 3, ac4 = f & 7;
            float* ap = As + arow * 36 + ac4 * 4;
            ap[0] = f2tf32(ra[i].x); ap[1] = f2tf32(ra[i].y);
            ap[2] = f2tf32(ra[i].z); ap[3] = f2tf32(ra[i].w);
            int browk = f >> 5, bc4 = f & 31;
            float* bp = Bs + browk * 132 + bc4 * 4;
            bp[0] = f2tf32(rb[i].x); bp[1] = f2tf32(rb[i].y);
            bp[2] = f2tf32(rb[i].z); bp[3] = f2tf32(rb[i].w);
        }
    };

    auto compute_tile = [&](int buf) {
        const float* As = AsBase + buf * ASZ;
        const float* Bs = BsBase + buf * BSZ;
        #pragma unroll
        for (int ks = 0; ks < 4; ks++) {
            const int k0 = ks * 8;
            uint32_t a[4][4];
            #pragma unroll
            for (int mi = 0; mi < 4; mi++) {
                const float* p = As + (warp_m * 64 + mi * 16 + lr) * 36 + k0 + lc;
                a[mi][0] = __float_as_uint(p[0]);
                a[mi][1] = __float_as_uint(p[8 * 36]);
                a[mi][2] = __float_as_uint(p[4]);
                a[mi][3] = __float_as_uint(p[8 * 36 + 4]);
            }
            uint32_t b[4][2];
            #pragma unroll
            for (int ni = 0; ni < 4; ni++) {
                const float* p = Bs + (k0 + lc) * 132 + warp_n * 32 + ni * 8 + lr;
                b[ni][0] = __float_as_uint(p[0]);
                b[ni][1] = __float_as_uint(p[4 * 132]);
            }
            #pragma unroll
            for (int mi = 0; mi < 4; mi++)
                #pragma unroll
                for (int ni = 0; ni < 4; ni++)
                    mma_tf32(acc[mi][ni], a[mi], b[ni]);
        }
    };

    const int nk = K / BKT;
    load_global(0);
    store_smem(0);
    __syncthreads();

    for (int kt = 0; kt < nk; kt++) {
        if (kt + 1 < nk) load_global(kt + 1);
        compute_tile(kt & 1);
        __syncthreads();
        if (kt + 1 < nk) {
            store_smem((kt + 1) & 1);
            __syncthreads();
        }
    }

    // Epilogue
    #pragma unroll
    for (int mi = 0; mi < 4; mi++) {
        #pragma unroll
        for (int ni = 0; ni < 4; ni++) {
            int r0 = brow + warp_m * 64 + mi * 16 + lr;
            int c0 = bcol + warp_n * 32 + ni * 8 + lc * 2;
            float2 v0 = make_float2(acc[mi][ni][0], acc[mi][ni][1]);
            float2 v1 = make_float2(acc[mi][ni][2], acc[mi][ni][3]);
            *(float2*)(C + (size_t)r0 * N + c0)       = v0;
            *(float2*)(C + (size_t)(r0 + 8) * N + c0) = v1;
        }
    }
}

// ---------------------------------------------------------------------------
// Fused: Bx = B_gate * x_proj; causal depthwise conv (L=3, per-batch);
//        y = C_gate * conv_out.
// ---------------------------------------------------------------------------
__global__ void conv_gate_kernel(const float* __restrict__ conv_w,
                                 float* __restrict__ y) {
    const size_t total = (size_t)BB * SS * (DD / 4);
    size_t idx = (size_t)blockIdx.x * blockDim.x + threadIdx.x;
    if (idx >= total) return;

    const int    d4 = (int)(idx % (DD / 4));
    const size_t bs = idx / (DD / 4);
    const int    s  = (int)(bs % SS);
    const int    d  = d4 * 4;

    const float* base = g_BCx + bs * TRIPLE;
    const float* bm1  = base - TRIPLE;
    const float* bm2  = base - 2 * TRIPLE;

    float out[4];
    #pragma unroll
    for (int j = 0; j < 4; j++) {
        const int dj = d + j;
        const float w0 = conv_w[dj * LL + 0];
        const float w1 = conv_w[dj * LL + 1];
        const float w2 = conv_w[dj * LL + 2];

        float bx_s  = base[dj] * base[2 * DD + dj];
        float bx_s1 = (s >= 1) ? bm1[dj] * bm1[2 * DD + dj] : 0.0f;
        float bx_s2 = (s >= 2) ? bm2[dj] * bm2[2 * DD + dj] : 0.0f;

        float conv = w2 * bx_s + w1 * bx_s1 + w0 * bx_s2;
        out[j] = base[DD + dj] * conv;
    }
    *(float4*)(g_y + bs * DD + d) = *(float4*)out;
}

// ---------------------------------------------------------------------------
extern "C" void kernel_launch(void* const* d_in, const int* in_sizes, int n_in,
                              void* d_out, int out_size) {
    const float* x      = (const float*)d_in[0];
    const float* W_in   = (const float*)d_in[1];
    const float* conv_w = (const float*)d_in[2];
    const float* W_out  = (const float*)d_in[3];
    float*       out    = (float*)d_out;

    float* BCx = nullptr;
    float* y   = nullptr;
    cudaGetSymbolAddress((void**)&BCx, g_BCx);
    cudaGetSymbolAddress((void**)&y,   g_y);

    cudaFuncSetAttribute(tf32_gemm, cudaFuncAttributeMaxDynamicSharedMemorySize, SMEM_BYTES);

    const int M = BB * SS;   // 16384

    // GEMM1: BCx = x @ W_in   (M x 2048) @ (2048 x 6144)
    {
        dim3 grid(TRIPLE / BN, M / BM);
        tf32_gemm<<<grid, 256, SMEM_BYTES>>>(x, W_in, BCx, TRIPLE, DD);
    }

    // Conv + gates -> y
    {
        const size_t total = (size_t)BB * SS * (DD / 4);
        int threads = 256;
        int blocks  = (int)((total + threads - 1) / threads);
        conv_gate_kernel<<<blocks, threads>>>(conv_w, y);
    }

    // GEMM2: out = y @ W_out  (M x 2048) @ (2048 x 2048)
    {
        dim3 grid(DD / BN, M / BM);
        tf32_gemm<<<grid, 256, SMEM_BYTES>>>(y, W_out, out, DD, DD);
    }
}

// round 4
// speedup vs baseline: 3.5703x; 1.9998x over previous
#include <cuda_runtime.h>
#include <cstdint>

// Problem constants
#define BB 4
#define SS 4096
#define DD 2048
#define LL 3
#define TRIPLE (3 * DD)
#define MTOT (BB * SS)          // 16384

// GEMM tiling: CTA 128x256, warp 64x64, BK=16, 8 warps, 4-stage cp.async
#define BM 128
#define BN 256
#define BK 16
#define NSTAGE 4
#define AST 20                  // A smem row stride (floats): 16 + 4 pad
#define BST 264                 // B smem row stride (floats): 256 + 8 pad
#define A_SM (BM * AST)         // 2560 floats
#define B_SM (BK * BST)         // 4224 floats
#define STG_FLT (A_SM + B_SM)   // 6784 floats
#define SMEM_BYTES (NSTAGE * STG_FLT * 4)   // 108544 B

// Scratch (__device__ globals: allocation-free rule)
__device__ float g_BCx[(size_t)BB * SS * TRIPLE];   // [b,s,3D] = [B_gate|C_gate|x_proj]
__device__ float g_y[(size_t)BB * SS * DD];         // GEMM2 A (tf32-rounded)
__device__ float g_xc[(size_t)BB * SS * DD];        // x tf32-rounded
__device__ float g_Win[(size_t)DD * TRIPLE];        // W_in  tf32-rounded
__device__ float g_Wout[(size_t)DD * DD];           // W_out tf32-rounded

__device__ __forceinline__ float f2tf32(float x) {
    float r;
    asm("cvt.rna.tf32.f32 %0, %1;" : "=f"(r) : "f"(x));
    return r;
}

__device__ __forceinline__ uint32_t smem_u32(const void* p) {
    uint32_t a;
    asm("{ .reg .u64 t; cvta.to.shared.u64 t, %1; cvt.u32.u64 %0, t; }" : "=r"(a) : "l"(p));
    return a;
}

#define CP_ASYNC16(dst, src) \
    asm volatile("cp.async.cg.shared.global [%0], [%1], 16;" :: "r"(dst), "l"(src))
#define CP_COMMIT() asm volatile("cp.async.commit_group;" ::: "memory")
#define CP_WAIT2()  asm volatile("cp.async.wait_group 2;" ::: "memory")

__device__ __forceinline__ void mma_tf32(float c[4], const uint32_t a[4], const uint32_t b[2]) {
    asm volatile(
        "mma.sync.aligned.m16n8k8.row.col.f32.tf32.tf32.f32 "
        "{%0,%1,%2,%3}, {%4,%5,%6,%7}, {%8,%9}, {%0,%1,%2,%3};"
        : "+f"(c[0]), "+f"(c[1]), "+f"(c[2]), "+f"(c[3])
        : "r"(a[0]), "r"(a[1]), "r"(a[2]), "r"(a[3]), "r"(b[0]), "r"(b[1]));
}

// ---------------------------------------------------------------------------
// TF32 mma.sync GEMM: C[M,N] = A[M,K] @ B[K,N], row-major fp32 (pre-rounded).
// 256 threads, warps 2x4, warp tile 64x64. M%128==0, N%256==0, K%16==0.
// ---------------------------------------------------------------------------
__global__ __launch_bounds__(256, 1)
void tf32_gemm(const float* __restrict__ A, const float* __restrict__ B,
               float* __restrict__ C, int N, int K) {
    extern __shared__ float sm[];
    const uint32_t smb = smem_u32(sm);

    const int tid    = threadIdx.x;
    const int wid    = tid >> 5;
    const int lane   = tid & 31;
    const int warp_m = wid >> 2;      // 0..1
    const int warp_n = wid & 3;       // 0..3
    const int lr     = lane >> 2;     // 0..7
    const int lc     = lane & 3;      // 0..3

    const int brow = blockIdx.y * BM;
    const int bcol = blockIdx.x * BN;

    const float* Ap = A + (size_t)brow * K;
    const float* Bp = B + bcol;

    // Per-thread cp.async coordinates
    const int am  = tid >> 2;               // A row for chunk (tid part)
    const int akc = (tid & 3) * 4;          // A k-offset within tile
    const int bkr = tid >> 6;               // B k row (tid part)
    const int bnc = (tid & 63) * 4;         // B n-offset

    auto issue = [&](int kt, int buf) {
        uint32_t as = smb + (uint32_t)buf * STG_FLT * 4;
        uint32_t bs = as + A_SM * 4;
        #pragma unroll
        for (int i = 0; i < 2; i++) {       // A: 128x16 = 512 chunks
            int m = am + i * 64;
            CP_ASYNC16(as + (uint32_t)(m * AST + akc) * 4,
                       Ap + (size_t)m * K + kt * BK + akc);
        }
        #pragma unroll
        for (int i = 0; i < 4; i++) {       // B: 16x256 = 1024 chunks
            int k = bkr + i * 4;
            CP_ASYNC16(bs + (uint32_t)(k * BST + bnc) * 4,
                       Bp + (size_t)(kt * BK + k) * N + bnc);
        }
    };

    float acc[4][8][4];
    #pragma unroll
    for (int mi = 0; mi < 4; mi++)
        #pragma unroll
        for (int ni = 0; ni < 8; ni++)
            #pragma unroll
            for (int t = 0; t < 4; t++)
                acc[mi][ni][t] = 0.0f;

    const int NK = K / BK;

    #pragma unroll
    for (int s = 0; s < NSTAGE - 1; s++) {
        issue(s, s);
        CP_COMMIT();
    }

    for (int kt = 0; kt < NK; kt++) {
        const int buf = kt & (NSTAGE - 1);
        CP_WAIT2();
        __syncthreads();

        if (kt + NSTAGE - 1 < NK) issue(kt + NSTAGE - 1, (kt + NSTAGE - 1) & (NSTAGE - 1));
        CP_COMMIT();

        const float* As = sm + (size_t)buf * STG_FLT;
        const float* Bs = As + A_SM;

        #pragma unroll
        for (int ks = 0; ks < 2; ks++) {
            const int k0 = ks * 8;
            uint32_t a[4][4];
            #pragma unroll
            for (int mi = 0; mi < 4; mi++) {
                const int base = (warp_m * 64 + mi * 16 + lr) * AST + k0 + lc;
                a[mi][0] = __float_as_uint(As[base]);
                a[mi][1] = __float_as_uint(As[base + 8 * AST]);
                a[mi][2] = __float_as_uint(As[base + 4]);
                a[mi][3] = __float_as_uint(As[base + 8 * AST + 4]);
            }
            uint32_t b[8][2];
            #pragma unroll
            for (int ni = 0; ni < 8; ni++) {
                const int base = (k0 + lc) * BST + warp_n * 64 + ni * 8 + lr;
                b[ni][0] = __float_as_uint(Bs[base]);
                b[ni][1] = __float_as_uint(Bs[base + 4 * BST]);
            }
            #pragma unroll
            for (int mi = 0; mi < 4; mi++)
                #pragma unroll
                for (int ni = 0; ni < 8; ni++)
                    mma_tf32(acc[mi][ni], a[mi], b[ni]);
        }
    }

    // Epilogue: per-fragment float2 stores
    #pragma unroll
    for (int mi = 0; mi < 4; mi++) {
        #pragma unroll
        for (int ni = 0; ni < 8; ni++) {
            const int r0 = brow + warp_m * 64 + mi * 16 + lr;
            const int c0 = bcol + warp_n * 64 + ni * 8 + lc * 2;
            *(float2*)(C + (size_t)r0 * N + c0)       = make_float2(acc[mi][ni][0], acc[mi][ni][1]);
            *(float2*)(C + (size_t)(r0 + 8) * N + c0) = make_float2(acc[mi][ni][2], acc[mi][ni][3]);
        }
    }
}

// ---------------------------------------------------------------------------
// Elementwise tf32 rounding (float4 vectorized)
// ---------------------------------------------------------------------------
__global__ void cvt_tf32_kernel(const float* __restrict__ in, float* __restrict__ out,
                                size_t n4) {
    size_t i = (size_t)blockIdx.x * blockDim.x + threadIdx.x;
    if (i >= n4) return;
    float4 v = ((const float4*)in)[i];
    v.x = f2tf32(v.x); v.y = f2tf32(v.y); v.z = f2tf32(v.z); v.w = f2tf32(v.w);
    ((float4*)out)[i] = v;
}

// ---------------------------------------------------------------------------
// Fused: Bx = B_gate*x_proj; causal L=3 depthwise conv; y = tf32(C_gate*conv)
// ---------------------------------------------------------------------------
__global__ void conv_gate_kernel(const float* __restrict__ conv_w,
                                 float* __restrict__ y) {
    const size_t total = (size_t)BB * SS * (DD / 4);
    size_t idx = (size_t)blockIdx.x * blockDim.x + threadIdx.x;
    if (idx >= total) return;

    const int    d4 = (int)(idx % (DD / 4));
    const size_t bs = idx / (DD / 4);
    const int    s  = (int)(bs % SS);
    const int    d  = d4 * 4;

    const float* bse = g_BCx + bs * TRIPLE;
    const float* bm1 = bse - TRIPLE;
    const float* bm2 = bse - 2 * TRIPLE;

    float out[4];
    #pragma unroll
    for (int j = 0; j < 4; j++) {
        const int dj = d + j;
        const float w0 = conv_w[dj * LL + 0];
        const float w1 = conv_w[dj * LL + 1];
        const float w2 = conv_w[dj * LL + 2];

        float bx_s  = bse[dj] * bse[2 * DD + dj];
        float bx_s1 = (s >= 1) ? bm1[dj] * bm1[2 * DD + dj] : 0.0f;
        float bx_s2 = (s >= 2) ? bm2[dj] * bm2[2 * DD + dj] : 0.0f;

        float conv = w2 * bx_s + w1 * bx_s1 + w0 * bx_s2;
        out[j] = f2tf32(bse[DD + dj] * conv);
    }
    *(float4*)(g_y + bs * DD + d) = *(float4*)out;
}

// ---------------------------------------------------------------------------
extern "C" void kernel_launch(void* const* d_in, const int* in_sizes, int n_in,
                              void* d_out, int out_size) {
    const float* x      = (const float*)d_in[0];
    const float* W_in   = (const float*)d_in[1];
    const float* conv_w = (const float*)d_in[2];
    const float* W_out  = (const float*)d_in[3];
    float*       out    = (float*)d_out;

    float *BCx, *y, *xc, *Win, *Wout;
    cudaGetSymbolAddress((void**)&BCx,  g_BCx);
    cudaGetSymbolAddress((void**)&y,    g_y);
    cudaGetSymbolAddress((void**)&xc,   g_xc);
    cudaGetSymbolAddress((void**)&Win,  g_Win);
    cudaGetSymbolAddress((void**)&Wout, g_Wout);

    cudaFuncSetAttribute(tf32_gemm, cudaFuncAttributeMaxDynamicSharedMemorySize, SMEM_BYTES);

    // Pre-round inputs to tf32 (rna) into scratch
    {
        size_t n4;
        n4 = (size_t)MTOT * DD / 4;
        cvt_tf32_kernel<<<(unsigned)((n4 + 255) / 256), 256>>>(x, xc, n4);
        n4 = (size_t)DD * TRIPLE / 4;
        cvt_tf32_kernel<<<(unsigned)((n4 + 255) / 256), 256>>>(W_in, Win, n4);
        n4 = (size_t)DD * DD / 4;
        cvt_tf32_kernel<<<(unsigned)((n4 + 255) / 256), 256>>>(W_out, Wout, n4);
    }

    // GEMM1: BCx = x' @ W_in'   (16384 x 2048) @ (2048 x 6144)
    tf32_gemm<<<dim3(TRIPLE / BN, MTOT / BM), 256, SMEM_BYTES>>>(xc, Win, BCx, TRIPLE, DD);

    // Conv + gates -> y (tf32-rounded)
    {
        size_t total = (size_t)BB * SS * (DD / 4);
        conv_gate_kernel<<<(unsigned)((total + 255) / 256), 256>>>(conv_w, y);
    }

    // GEMM2: out = y @ W_out'   (16384 x 2048) @ (2048 x 2048)
    tf32_gemm<<<dim3(DD / BN, MTOT / BM), 256, SMEM_BYTES>>>(y, Wout, out, DD, DD);
}